// round 3
// baseline (speedup 1.0000x reference)
#include <cuda_runtime.h>
#include <cstdint>

// ============================================================================
// LSTM_34883724378521 : T=60, C=H=128, N=4096, TOUT=114
// Persistent-kernel tf32 mma.sync path. 128 CTAs (4 gate-tiles x 32 batch-
// tiles), weights resident in smem, c-state in registers, 4-CTA group barrier
// per timestep (groups are independent across batch tiles).
// ============================================================================
#define NB 4096
#define HD 128
#define NG 512

__device__ __forceinline__ uint32_t smem_u32(const void* p) {
    uint32_t a;
    asm("{ .reg .u64 t; cvta.to.shared.u64 t, %1; cvt.u32.u64 %0, t; }"
        : "=r"(a) : "l"(p));
    return a;
}
__device__ __forceinline__ void cp16cg(uint32_t dst, const void* src) {
    asm volatile("cp.async.cg.shared.global [%0], [%1], 16;" :: "r"(dst), "l"(src));
}
#define CP_COMMIT() asm volatile("cp.async.commit_group;" ::: "memory")
#define CP_WAIT(n)  asm volatile("cp.async.wait_group %0;" :: "n"(n) : "memory")

__device__ __forceinline__ uint32_t rna_tf32(float v) {
    uint32_t u; asm("cvt.rna.tf32.f32 %0, %1;" : "=r"(u) : "f"(v)); return u;
}
__device__ __forceinline__ void mma8(float* d, const uint32_t* a, const uint32_t* b) {
    asm volatile(
        "mma.sync.aligned.m16n8k8.row.col.f32.tf32.tf32.f32 "
        "{%0,%1,%2,%3}, {%4,%5,%6,%7}, {%8,%9}, {%0,%1,%2,%3};"
        : "+f"(d[0]), "+f"(d[1]), "+f"(d[2]), "+f"(d[3])
        : "r"(a[0]), "r"(a[1]), "r"(a[2]), "r"(a[3]), "r"(b[0]), "r"(b[1]));
}
__device__ __forceinline__ float sigf(float x)   { return 1.0f / (1.0f + __expf(-x)); }
__device__ __forceinline__ float tanhf_(float x) { return 1.0f - 2.0f / (__expf(2.0f * x) + 1.0f); }

// ---------------------------------------------------------------------------
// persistent device state
// ---------------------------------------------------------------------------
__device__ float    g_Hbuf0[HD * NB];   // h state, h-major [H][N], ping
__device__ float    g_Hbuf1[HD * NB];   // pong
__device__ float    g_W1[NG * 256];     // permuted [4h+g][x|h], tf32-rounded
__device__ float    g_bias[NG];         // permuted b_ih + b_hh
__device__ unsigned g_bar[32];          // per-batch-group step counters

// ---------------------------------------------------------------------------
// prep: permute rows (r = 4*h + g  <-  g*128 + h), RNA-round, zero state/bars
// ---------------------------------------------------------------------------
__global__ void prep_kernel(const float* __restrict__ Wih, const float* __restrict__ Whh,
                            const float* __restrict__ bih, const float* __restrict__ bhh) {
    int tid = blockIdx.x * 256 + threadIdx.x;       // 512*256 = 131072
    int r = tid >> 8, k = tid & 255;
    int h = r >> 2, g = r & 3;
    int orig = g * HD + h;
    float v = (k < 128) ? Wih[orig * HD + k] : Whh[orig * HD + (k - 128)];
    g_W1[r * 256 + k] = __uint_as_float(rna_tf32(v));
    if (k == 0) g_bias[r] = bih[orig] + bhh[orig];
    if (tid < 32) g_bar[tid] = 0u;
    for (int i = tid; i < HD * NB; i += 131072) g_Hbuf0[i] = 0.0f;
}

// ---------------------------------------------------------------------------
// smem layout (float offsets)
// ---------------------------------------------------------------------------
static constexpr int OFF_BIAS = 0;                       // 128 floats
static constexpr int OFF_B    = 128;                     // 128 rows * 260
static constexpr int OFF_A0   = OFF_B + 128 * 260;       // 32 k-rows * 136
static constexpr int OFF_A1   = OFF_A0 + 32 * 136;
static constexpr int SM_FLOATS = OFF_A1 + 32 * 136;
static constexpr int SM_BYTES  = SM_FLOATS * 4;          // 168448 B

__global__ void __launch_bounds__(256, 1)
lstm_persist(const float* __restrict__ img, float* __restrict__ out, int T, int TOUT) {
    extern __shared__ float smf[];
    const uint32_t sb = smem_u32(smf);
    const int tid = threadIdx.x, lane = tid & 31, wid = tid >> 5;
    const int gq = lane >> 2, tig = lane & 3;
    const int wm = wid >> 1, wn = wid & 1;
    const int j = blockIdx.x, mb = blockIdx.y, n0 = mb * 128;

    // bias + resident weights (once)
    if (tid < 128) smf[OFF_BIAS + tid] = g_bias[j * 128 + tid];
    for (int i = tid; i < 128 * 64; i += 256) {
        int r = i >> 6, q = (i & 63) << 2;
        cp16cg(sb + (uint32_t)(OFF_B + r * 260 + q) * 4,
               g_W1 + (size_t)(j * 128 + r) * 256 + q);
    }
    CP_COMMIT();

    float c[16];
    #pragma unroll
    for (int i = 0; i < 16; i++) c[i] = 0.0f;

    CP_WAIT(0);
    __syncthreads();

    for (int t = 0; t < TOUT; t++) {
        const float* hprev = (t & 1) ? g_Hbuf1 : g_Hbuf0;
        float*       hnext = (t & 1) ? g_Hbuf0 : g_Hbuf1;
        const bool p1 = (t < T);
        const float* xs = img + (size_t)t * HD * NB;
        const int nch = p1 ? 8 : 4;

        float acc[2][8][4];
        #pragma unroll
        for (int a0 = 0; a0 < 2; a0++)
            #pragma unroll
            for (int a1 = 0; a1 < 8; a1++)
                #pragma unroll
                for (int a2 = 0; a2 < 4; a2++) acc[a0][a1][a2] = 0.0f;

        // ---- chunk loader (A tile: 32 k-rows x 128 m) ----
        auto loadA = [&](int ci) {
            const uint32_t bb = sb + (uint32_t)((ci & 1) ? OFF_A1 : OFF_A0) * 4;
            const float* src;
            int kr;
            if (p1 && ci < 4) { src = xs;    kr = ci * 32; }
            else              { src = hprev; kr = (p1 ? ci - 4 : ci) * 32; }
            #pragma unroll
            for (int it = 0; it < 4; it++) {
                int idx = tid + it * 256;
                int kk = idx >> 5, mp = (idx & 31) << 2;
                cp16cg(bb + (uint32_t)(kk * 136 + mp) * 4,
                       src + (size_t)(kr + kk) * NB + n0 + mp);
            }
            CP_COMMIT();
        };

        loadA(0);
        for (int ci = 0; ci < nch; ci++) {
            if (ci + 1 < nch) { loadA(ci + 1); CP_WAIT(1); } else { CP_WAIT(0); }
            __syncthreads();
            const float* As = smf + ((ci & 1) ? OFF_A1 : OFF_A0);
            const bool docvt = p1 && ci < 4;      // img chunks need tf32 rounding

            #pragma unroll
            for (int kc = 0; kc < 4; kc++) {
                const int k0 = kc * 8;
                uint32_t a[2][4];
                #pragma unroll
                for (int mt = 0; mt < 2; mt++) {
                    const int r0 = wm * 32 + mt * 16 + gq;
                    float v0 = As[(k0 + tig) * 136 + r0];
                    float v1 = As[(k0 + tig) * 136 + r0 + 8];
                    float v2 = As[(k0 + tig + 4) * 136 + r0];
                    float v3 = As[(k0 + tig + 4) * 136 + r0 + 8];
                    if (docvt) {
                        a[mt][0] = rna_tf32(v0); a[mt][1] = rna_tf32(v1);
                        a[mt][2] = rna_tf32(v2); a[mt][3] = rna_tf32(v3);
                    } else {
                        a[mt][0] = __float_as_uint(v0); a[mt][1] = __float_as_uint(v1);
                        a[mt][2] = __float_as_uint(v2); a[mt][3] = __float_as_uint(v3);
                    }
                }
                const int npass = p1 ? 1 : 2;     // phase2: W_ih cols + W_hh cols
                for (int ps = 0; ps < npass; ps++) {
                    const float* Bp = smf + OFF_B + ci * 32 + ps * 128;
                    #pragma unroll
                    for (int nt = 0; nt < 8; nt++) {
                        const int c0 = wn * 64 + nt * 8 + gq;
                        uint32_t b[2];
                        b[0] = __float_as_uint(Bp[c0 * 260 + k0 + tig]);
                        b[1] = __float_as_uint(Bp[c0 * 260 + k0 + tig + 4]);
                        mma8(acc[0][nt], a[0], b);
                        mma8(acc[1][nt], a[1], b);
                    }
                }
            }
            __syncthreads();
        }

        // ---- epilogue: shuffle gate quads together, cell update, stage h ----
        float* H2 = smf + OFF_A0;                 // 32*129 floats, aliases A bufs
        const int mymt = tig & 1;                 // even lanes: rows of mt=0
        const int r0e = wm * 32 + mymt * 16 + gq;
        #pragma unroll
        for (int nt = 0; nt < 8; nt++) {
            const int u = wn * 16 + nt * 2 + (tig >> 1);
            float oth[4];
            #pragma unroll
            for (int e = 0; e < 4; e++)
                oth[e] = __shfl_xor_sync(0xffffffffu, acc[mymt ^ 1][nt][e], 1);
            const float b0 = smf[OFF_BIAS + 4 * u + 0];
            const float b1 = smf[OFF_BIAS + 4 * u + 1];
            const float b2 = smf[OFF_BIAS + 4 * u + 2];
            const float b3 = smf[OFF_BIAS + 4 * u + 3];
            #pragma unroll
            for (int e2 = 0; e2 < 2; e2++) {
                const float ow0 = acc[mymt][nt][2 * e2], ow1 = acc[mymt][nt][2 * e2 + 1];
                const float ot0 = oth[2 * e2],           ot1 = oth[2 * e2 + 1];
                float gi, gf, gg, go;
                if (mymt == 0) { gi = ow0; gf = ow1; gg = ot0; go = ot1; }
                else           { gg = ow0; go = ow1; gi = ot0; gf = ot1; }
                gi += b0; gf += b1; gg += b2; go += b3;
                const int cidx = nt * 2 + e2;
                const float cn = sigf(gf) * c[cidx] + sigf(gi) * tanhf_(gg);
                c[cidx] = cn;
                H2[u * 129 + r0e + 8 * e2] = sigf(go) * tanhf_(cn);
            }
        }
        __syncthreads();

        // ---- h-state writeback (h-major, pre-rounded to tf32) ----
        #pragma unroll
        for (int q = 0; q < 4; q++) {
            const int u = wid * 4 + q;
            #pragma unroll
            for (int mk = 0; mk < 4; mk++) {
                const int m = mk * 32 + lane;
                hnext[(size_t)(j * 32 + u) * NB + n0 + m] =
                    __uint_as_float(rna_tf32(H2[u * 129 + m]));
            }
        }
        // ---- output writeback: out[n][t][h], 128B contiguous ----
        #pragma unroll
        for (int i2 = 0; i2 < 16; i2++) {
            const int mr = wid * 16 + i2;
            out[(size_t)(n0 + mr) * TOUT * HD + (size_t)t * HD + j * 32 + lane] =
                H2[lane * 129 + mr];
        }

        // ---- 4-CTA group barrier (groups independent across batch tiles) ----
        if (t + 1 < TOUT) {
            __threadfence();
            __syncthreads();
            if (tid == 0) {
                unsigned* bp = &g_bar[mb];
                asm volatile("red.release.gpu.add.u32 [%0], %1;"
                             :: "l"(bp), "r"(1u) : "memory");
                const unsigned target = 4u * (unsigned)(t + 1);
                unsigned v = 0;
                do {
                    asm volatile("ld.acquire.gpu.u32 %0, [%1];"
                                 : "=r"(v) : "l"(bp) : "memory");
                } while (v < target);
            }
            __syncthreads();
        }
    }
}

// ---------------------------------------------------------------------------
// launch: prep + one persistent kernel
// ---------------------------------------------------------------------------
extern "C" void kernel_launch(void* const* d_in, const int* in_sizes, int n_in,
                              void* d_out, int out_size) {
    const float* img = (const float*)d_in[0];
    const float* Wih = (const float*)d_in[2];
    const float* Whh = (const float*)d_in[3];
    const float* bih = (const float*)d_in[4];
    const float* bhh = (const float*)d_in[5];
    float* out = (float*)d_out;

    const int T    = in_sizes[0] / (HD * NB);       // 60
    const int TOUT = out_size / (NB * HD);          // 114

    cudaFuncSetAttribute((const void*)lstm_persist,
                         cudaFuncAttributeMaxDynamicSharedMemorySize, SM_BYTES);

    prep_kernel<<<512, 256>>>(Wih, Whh, bih, bhh);

    dim3 grid(4, NB / 128);                         // 128 CTAs, all co-resident
    lstm_persist<<<grid, 256, SM_BYTES>>>(img, out, T, TOUT);
}

// round 4
// speedup vs baseline: 2.3180x; 2.3180x over previous
#include <cuda_runtime.h>
#include <cstdint>

// ============================================================================
// LSTM_34883724378521 : T=60, C=H=128, N=4096, TOUT=114
// Multi-kernel tf32 mma.sync path, 3-stage cp.async pipeline, shuffle epilogue.
// grid = (4 gate tiles, 32 batch tiles), 256 threads, 1 kernel per timestep.
// ============================================================================
#define NB 4096
#define HD 128
#define NG 512

__device__ __forceinline__ uint32_t smem_u32(const void* p) {
    uint32_t a;
    asm("{ .reg .u64 t; cvta.to.shared.u64 t, %1; cvt.u32.u64 %0, t; }"
        : "=r"(a) : "l"(p));
    return a;
}
__device__ __forceinline__ void cp16(uint32_t dst, const void* src) {
    asm volatile("cp.async.cg.shared.global [%0], [%1], 16;" :: "r"(dst), "l"(src));
}
#define CP_COMMIT() asm volatile("cp.async.commit_group;" ::: "memory")
#define CP_WAIT(n)  asm volatile("cp.async.wait_group %0;" :: "n"(n) : "memory")

__device__ __forceinline__ uint32_t rna_tf32(float v) {
    uint32_t u; asm("cvt.rna.tf32.f32 %0, %1;" : "=r"(u) : "f"(v)); return u;
}
__device__ __forceinline__ void mma8(float* d, const uint32_t* a, const uint32_t* b) {
    asm volatile(
        "mma.sync.aligned.m16n8k8.row.col.f32.tf32.tf32.f32 "
        "{%0,%1,%2,%3}, {%4,%5,%6,%7}, {%8,%9}, {%0,%1,%2,%3};"
        : "+f"(d[0]), "+f"(d[1]), "+f"(d[2]), "+f"(d[3])
        : "r"(a[0]), "r"(a[1]), "r"(a[2]), "r"(a[3]), "r"(b[0]), "r"(b[1]));
}
__device__ __forceinline__ float sigf(float x)   { return 1.0f / (1.0f + __expf(-x)); }
__device__ __forceinline__ float tanhf_(float x) { return 1.0f - 2.0f / (__expf(2.0f * x) + 1.0f); }

// ---------------------------------------------------------------------------
// persistent device state
// ---------------------------------------------------------------------------
__device__ float g_Hbuf0[HD * NB];   // h state, h-major [H][N] (tf32-rounded)
__device__ float g_Hbuf1[HD * NB];
__device__ float g_Cbuf [HD * NB];   // c state, h-major
__device__ float g_W1[NG * 256];     // permuted [4h+g][x|h], tf32-rounded
__device__ float g_W2[NG * 128];     // permuted (W_ih+W_hh), tf32-rounded
__device__ float g_bias[NG];         // permuted b_ih + b_hh

// ---------------------------------------------------------------------------
// prep: row perm r = 4*h+g  <-  g*128+h ; RNA-round weights; zero state
// ---------------------------------------------------------------------------
__global__ void prep_kernel(const float* __restrict__ Wih, const float* __restrict__ Whh,
                            const float* __restrict__ bih, const float* __restrict__ bhh) {
    int tid = blockIdx.x * 256 + threadIdx.x;       // 512*256 = 131072
    int r = tid >> 8, k = tid & 255;
    int h = r >> 2, g = r & 3;
    int orig = g * HD + h;
    float v = (k < 128) ? Wih[orig * HD + k] : Whh[orig * HD + (k - 128)];
    g_W1[r * 256 + k] = __uint_as_float(rna_tf32(v));
    if (k < 128)
        g_W2[r * 128 + k] =
            __uint_as_float(rna_tf32(Wih[orig * HD + k] + Whh[orig * HD + k]));
    if (k == 0) g_bias[r] = bih[orig] + bhh[orig];
    for (int i = tid; i < HD * NB; i += 131072) {
        g_Hbuf0[i] = 0.0f;
        g_Cbuf[i]  = 0.0f;
    }
}

// ---------------------------------------------------------------------------
// smem layout (float offsets): bias | 3x A(32x136) | 3x B(128x36); H2 aliases A
// ---------------------------------------------------------------------------
static constexpr int A_STR = 136, B_STR = 36;
static constexpr int A_FL  = 32 * A_STR;      // 4352
static constexpr int B_FL  = 128 * B_STR;     // 4608
static constexpr int OFF_BIAS = 0;
static constexpr int OFF_A    = 128;
static constexpr int OFF_B    = OFF_A + 3 * A_FL;
static constexpr int SM_FLOATS = OFF_B + 3 * B_FL;
static constexpr int SM_BYTES  = SM_FLOATS * 4;   // ~108 KB

// ---------------------------------------------------------------------------
// fused step. CTA tile M=128 x N=128, K = NCH*32. NCH=8 (phase1) / 4 (phase2)
// ---------------------------------------------------------------------------
template <int NCH>
__global__ void __launch_bounds__(256, 1)
lstm_step(const float* __restrict__ xsrc,   // [128][NB] x_t slice or null
          const float* __restrict__ hprev,  // [128][NB] (pre-rounded tf32)
          float* __restrict__ hnext,
          float* __restrict__ out, int t_out, int TOUT) {
    extern __shared__ float smf[];
    const uint32_t sb = smem_u32(smf);
    const int tid = threadIdx.x, lane = tid & 31, wid = tid >> 5;
    const int gq = lane >> 2, tig = lane & 3;
    const int wm = wid >> 1, wn = wid & 1;
    const int j = blockIdx.x, n0 = blockIdx.y * 128;

    if (tid < 128) smf[OFF_BIAS + tid] = g_bias[j * 128 + tid];

    const float* W = (NCH == 8) ? g_W1 : g_W2;
    const int KT = NCH * 32;

    auto loadC = [&](int ch) {
        const int buf = ch % 3;
        const float* asrc = (NCH == 8 && ch < 4) ? xsrc : hprev;
        const int kr = (NCH == 8 && ch >= 4) ? (ch - 4) * 32 : ch * 32;
        const uint32_t ab = sb + (uint32_t)(OFF_A + buf * A_FL) * 4;
        const uint32_t bb = sb + (uint32_t)(OFF_B + buf * B_FL) * 4;
        #pragma unroll
        for (int it = 0; it < 4; it++) {
            int idx = tid + it * 256;
            {   // A: 32 k-rows x 128 m
                int kk = idx >> 5, mp = (idx & 31) << 2;
                cp16(ab + (uint32_t)(kk * A_STR + mp) * 4,
                     asrc + (size_t)(kr + kk) * NB + n0 + mp);
            }
            {   // B: 128 gate-cols x 32 k
                int n = idx >> 3, q = (idx & 7) << 2;
                cp16(bb + (uint32_t)(n * B_STR + q) * 4,
                     W + (size_t)(j * 128 + n) * KT + ch * 32 + q);
            }
        }
        CP_COMMIT();
    };

    float acc[2][8][4];
    #pragma unroll
    for (int a0 = 0; a0 < 2; a0++)
        #pragma unroll
        for (int a1 = 0; a1 < 8; a1++)
            #pragma unroll
            for (int a2 = 0; a2 < 4; a2++) acc[a0][a1][a2] = 0.0f;

    loadC(0);
    loadC(1);
    #pragma unroll
    for (int ch = 0; ch < NCH; ch++) {
        if (ch == NCH - 1) { CP_WAIT(0); } else { CP_WAIT(1); }
        __syncthreads();                       // chunk ch ready; mma(ch-1) done
        if (ch + 2 < NCH) loadC(ch + 2);       // safe: writes buf not in use
        const float* As = smf + OFF_A + (ch % 3) * A_FL;
        const float* Bs = smf + OFF_B + (ch % 3) * B_FL;
        const bool docvt = (NCH == 8 && ch < 4);   // img chunks need rounding

        #pragma unroll
        for (int kc = 0; kc < 4; kc++) {
            const int k0 = kc * 8;
            uint32_t a[2][4];
            #pragma unroll
            for (int mt = 0; mt < 2; mt++) {
                const int r0 = wm * 32 + mt * 16 + gq;
                float v0 = As[(k0 + tig) * A_STR + r0];
                float v1 = As[(k0 + tig) * A_STR + r0 + 8];
                float v2 = As[(k0 + tig + 4) * A_STR + r0];
                float v3 = As[(k0 + tig + 4) * A_STR + r0 + 8];
                if (docvt) {
                    a[mt][0] = rna_tf32(v0); a[mt][1] = rna_tf32(v1);
                    a[mt][2] = rna_tf32(v2); a[mt][3] = rna_tf32(v3);
                } else {
                    a[mt][0] = __float_as_uint(v0); a[mt][1] = __float_as_uint(v1);
                    a[mt][2] = __float_as_uint(v2); a[mt][3] = __float_as_uint(v3);
                }
            }
            #pragma unroll
            for (int nt = 0; nt < 8; nt++) {
                const int c0 = wn * 64 + nt * 8 + gq;
                uint32_t b[2];
                b[0] = __float_as_uint(Bs[c0 * B_STR + k0 + tig]);
                b[1] = __float_as_uint(Bs[c0 * B_STR + k0 + tig + 4]);
                mma8(acc[0][nt], a[0], b);
                mma8(acc[1][nt], a[1], b);
            }
        }
    }
    __syncthreads();     // all mma done -> safe to reuse A bufs as H2 stage

    // ---- shuffle epilogue: pair (i,f) with (g,o) via lane^1 ----
    float* H2 = smf + OFF_A;            // 32 units x 129 stride
    const int mymt = tig & 1;
    const int r0e = wm * 32 + mymt * 16 + gq;
    #pragma unroll
    for (int nt = 0; nt < 8; nt++) {
        const int u = wn * 16 + nt * 2 + (tig >> 1);
        float oth[4];
        #pragma unroll
        for (int e = 0; e < 4; e++)
            oth[e] = __shfl_xor_sync(0xffffffffu, acc[mymt ^ 1][nt][e], 1);
        const float b0 = smf[OFF_BIAS + 4 * u + 0];
        const float b1 = smf[OFF_BIAS + 4 * u + 1];
        const float b2 = smf[OFF_BIAS + 4 * u + 2];
        const float b3 = smf[OFF_BIAS + 4 * u + 3];
        #pragma unroll
        for (int e2 = 0; e2 < 2; e2++) {
            const float ow0 = acc[mymt][nt][2 * e2], ow1 = acc[mymt][nt][2 * e2 + 1];
            const float ot0 = oth[2 * e2],           ot1 = oth[2 * e2 + 1];
            float gi, gf, gg, go;
            if (mymt == 0) { gi = ow0; gf = ow1; gg = ot0; go = ot1; }
            else           { gg = ow0; go = ow1; gi = ot0; gf = ot1; }
            gi += b0; gf += b1; gg += b2; go += b3;
            const int row = r0e + 8 * e2;
            const size_t ci = (size_t)(j * 32 + u) * NB + n0 + row;
            const float cold = g_Cbuf[ci];
            const float cn = sigf(gf) * cold + sigf(gi) * tanhf_(gg);
            g_Cbuf[ci] = cn;
            H2[u * 129 + row] = sigf(go) * tanhf_(cn);
        }
    }
    __syncthreads();

    // ---- h-state writeback (h-major, pre-rounded to tf32) ----
    #pragma unroll
    for (int q = 0; q < 4; q++) {
        const int u = wid * 4 + q;
        #pragma unroll
        for (int mk = 0; mk < 4; mk++) {
            const int m = mk * 32 + lane;
            hnext[(size_t)(j * 32 + u) * NB + n0 + m] =
                __uint_as_float(rna_tf32(H2[u * 129 + m]));
        }
    }
    // ---- output writeback: out[n][t][h], 128B contiguous ----
    #pragma unroll
    for (int i2 = 0; i2 < 16; i2++) {
        const int mr = wid * 16 + i2;
        out[(size_t)(n0 + mr) * TOUT * HD + (size_t)t_out * HD + j * 32 + lane] =
            H2[lane * 129 + mr];
    }
}

// ---------------------------------------------------------------------------
// launch: prep + 60 K=256 steps + 54 K=128 steps
// ---------------------------------------------------------------------------
extern "C" void kernel_launch(void* const* d_in, const int* in_sizes, int n_in,
                              void* d_out, int out_size) {
    const float* img = (const float*)d_in[0];
    const float* Wih = (const float*)d_in[2];
    const float* Whh = (const float*)d_in[3];
    const float* bih = (const float*)d_in[4];
    const float* bhh = (const float*)d_in[5];
    float* out = (float*)d_out;

    const int T    = in_sizes[0] / (HD * NB);       // 60
    const int TOUT = out_size / (NB * HD);          // 114

    void *h0p, *h1p;
    cudaGetSymbolAddress(&h0p, g_Hbuf0);
    cudaGetSymbolAddress(&h1p, g_Hbuf1);
    float* hb[2] = {(float*)h0p, (float*)h1p};

    cudaFuncSetAttribute((const void*)lstm_step<8>,
                         cudaFuncAttributeMaxDynamicSharedMemorySize, SM_BYTES);
    cudaFuncSetAttribute((const void*)lstm_step<4>,
                         cudaFuncAttributeMaxDynamicSharedMemorySize, SM_BYTES);

    prep_kernel<<<512, 256>>>(Wih, Whh, bih, bhh);

    dim3 grid(4, NB / 128);
    for (int t = 0; t < TOUT; t++) {
        float* hp = hb[t & 1];
        float* hn = hb[(t + 1) & 1];
        if (t < T) {
            lstm_step<8><<<grid, 256, SM_BYTES>>>(
                img + (size_t)t * HD * NB, hp, hn, out, t, TOUT);
        } else {
            lstm_step<4><<<grid, 256, SM_BYTES>>>(
                nullptr, hp, hn, out, t, TOUT);
        }
    }
}

// round 5
// speedup vs baseline: 3.3361x; 1.4392x over previous
#include <cuda_runtime.h>
#include <cstdint>

// ============================================================================
// LSTM_34883724378521 : T=60, C=H=128, N=4096, TOUT=114
// tf32 mma.sync, 1 kernel/step. grid = (8 gate tiles x 32 batch tiles) = 256
// CTAs -> 2 CTAs/SM (16 warps/SM) for latency hiding. CTA tile M=128 x N=64.
// ============================================================================
#define NB 4096
#define HD 128
#define NG 512

__device__ __forceinline__ uint32_t smem_u32(const void* p) {
    uint32_t a;
    asm("{ .reg .u64 t; cvta.to.shared.u64 t, %1; cvt.u32.u64 %0, t; }"
        : "=r"(a) : "l"(p));
    return a;
}
__device__ __forceinline__ void cp16(uint32_t dst, const void* src) {
    asm volatile("cp.async.cg.shared.global [%0], [%1], 16;" :: "r"(dst), "l"(src));
}
#define CP_COMMIT() asm volatile("cp.async.commit_group;" ::: "memory")
#define CP_WAIT(n)  asm volatile("cp.async.wait_group %0;" :: "n"(n) : "memory")

__device__ __forceinline__ uint32_t rna_tf32(float v) {
    uint32_t u; asm("cvt.rna.tf32.f32 %0, %1;" : "=r"(u) : "f"(v)); return u;
}
__device__ __forceinline__ void mma8(float* d, const uint32_t* a, const uint32_t* b) {
    asm volatile(
        "mma.sync.aligned.m16n8k8.row.col.f32.tf32.tf32.f32 "
        "{%0,%1,%2,%3}, {%4,%5,%6,%7}, {%8,%9}, {%0,%1,%2,%3};"
        : "+f"(d[0]), "+f"(d[1]), "+f"(d[2]), "+f"(d[3])
        : "r"(a[0]), "r"(a[1]), "r"(a[2]), "r"(a[3]), "r"(b[0]), "r"(b[1]));
}
__device__ __forceinline__ float sigf(float x)   { return 1.0f / (1.0f + __expf(-x)); }
__device__ __forceinline__ float tanhf_(float x) { return 1.0f - 2.0f / (__expf(2.0f * x) + 1.0f); }

// ---------------------------------------------------------------------------
// persistent device state
// ---------------------------------------------------------------------------
__device__ float g_Hbuf0[HD * NB];   // h state, h-major [H][N] (tf32-rounded)
__device__ float g_Hbuf1[HD * NB];
__device__ float g_Cbuf [HD * NB];   // c state, h-major
__device__ float g_W1[NG * 256];     // permuted [4h+g][x|h], tf32-rounded
__device__ float g_W2[NG * 128];     // permuted (W_ih+W_hh), tf32-rounded
__device__ float g_bias[NG];         // permuted b_ih + b_hh

// ---------------------------------------------------------------------------
// prep: row perm r = 4*h+g  <-  g*128+h ; RNA-round weights; zero state
// ---------------------------------------------------------------------------
__global__ void prep_kernel(const float* __restrict__ Wih, const float* __restrict__ Whh,
                            const float* __restrict__ bih, const float* __restrict__ bhh) {
    int tid = blockIdx.x * 256 + threadIdx.x;       // 512*256 = 131072
    int r = tid >> 8, k = tid & 255;
    int h = r >> 2, g = r & 3;
    int orig = g * HD + h;
    float v = (k < 128) ? Wih[orig * HD + k] : Whh[orig * HD + (k - 128)];
    g_W1[r * 256 + k] = __uint_as_float(rna_tf32(v));
    if (k < 128)
        g_W2[r * 128 + k] =
            __uint_as_float(rna_tf32(Wih[orig * HD + k] + Whh[orig * HD + k]));
    if (k == 0) g_bias[r] = bih[orig] + bhh[orig];
    for (int i = tid; i < HD * NB; i += 131072) {
        g_Hbuf0[i] = 0.0f;
        g_Cbuf[i]  = 0.0f;
    }
}

// ---------------------------------------------------------------------------
// smem layout (float offsets): bias(64) | 3x A(32x136) | 3x B(64x36)
// H2 stage (16 units x 130) aliases the A buffers after the mainloop.
// ---------------------------------------------------------------------------
static constexpr int A_STR = 136, B_STR = 36, H_STR = 130;
static constexpr int A_FL  = 32 * A_STR;      // 4352
static constexpr int B_FL  = 64 * B_STR;      // 2304
static constexpr int OFF_BIAS = 0;
static constexpr int OFF_A    = 64;
static constexpr int OFF_B    = OFF_A + 3 * A_FL;
static constexpr int SM_FLOATS = OFF_B + 3 * B_FL;
static constexpr int SM_BYTES  = SM_FLOATS * 4;   // 79936 B -> 2 CTAs/SM

// ---------------------------------------------------------------------------
// fused step. CTA tile M=128 x N=64 (16 hidden units), K = NCH*32.
// ---------------------------------------------------------------------------
template <int NCH>
__global__ void __launch_bounds__(256, 2)
lstm_step(const float* __restrict__ xsrc,   // [128][NB] x_t slice or null
          const float* __restrict__ hprev,  // [128][NB] (pre-rounded tf32)
          float* __restrict__ hnext,
          float* __restrict__ out, int t_out, int TOUT) {
    extern __shared__ float smf[];
    const uint32_t sb = smem_u32(smf);
    const int tid = threadIdx.x, lane = tid & 31, wid = tid >> 5;
    const int gq = lane >> 2, tig = lane & 3;
    const int wm = wid >> 1, wn = wid & 1;            // 4 x 2 warp grid
    const int j = blockIdx.x, n0 = blockIdx.y * 128;  // j: 64 gate cols

    if (tid < 64) smf[OFF_BIAS + tid] = g_bias[j * 64 + tid];

    const float* W = (NCH == 8) ? g_W1 : g_W2;
    const int KT = NCH * 32;

    auto loadC = [&](int ch) {
        const int buf = ch % 3;
        const float* asrc = (NCH == 8 && ch < 4) ? xsrc : hprev;
        const int kr = (NCH == 8 && ch >= 4) ? (ch - 4) * 32 : ch * 32;
        const uint32_t ab = sb + (uint32_t)(OFF_A + buf * A_FL) * 4;
        const uint32_t bb = sb + (uint32_t)(OFF_B + buf * B_FL) * 4;
        #pragma unroll
        for (int it = 0; it < 4; it++) {   // A: 32 k-rows x 128 m
            int idx = tid + it * 256;
            int kk = idx >> 5, mp = (idx & 31) << 2;
            cp16(ab + (uint32_t)(kk * A_STR + mp) * 4,
                 asrc + (size_t)(kr + kk) * NB + n0 + mp);
        }
        #pragma unroll
        for (int it = 0; it < 2; it++) {   // B: 64 gate-cols x 32 k
            int idx = tid + it * 256;
            int n = idx >> 3, q = (idx & 7) << 2;
            cp16(bb + (uint32_t)(n * B_STR + q) * 4,
                 W + (size_t)(j * 64 + n) * KT + ch * 32 + q);
        }
        CP_COMMIT();
    };

    float acc[2][4][4];
    #pragma unroll
    for (int a0 = 0; a0 < 2; a0++)
        #pragma unroll
        for (int a1 = 0; a1 < 4; a1++)
            #pragma unroll
            for (int a2 = 0; a2 < 4; a2++) acc[a0][a1][a2] = 0.0f;

    loadC(0);
    loadC(1);
    #pragma unroll
    for (int ch = 0; ch < NCH; ch++) {
        if (ch == NCH - 1) { CP_WAIT(0); } else { CP_WAIT(1); }
        __syncthreads();                       // chunk ch ready; mma(ch-1) done
        if (ch + 2 < NCH) loadC(ch + 2);
        const float* As = smf + OFF_A + (ch % 3) * A_FL;
        const float* Bs = smf + OFF_B + (ch % 3) * B_FL;
        const bool docvt = (NCH == 8 && ch < 4);

        #pragma unroll
        for (int kc = 0; kc < 4; kc++) {
            const int k0 = kc * 8;
            uint32_t a[2][4];
            #pragma unroll
            for (int mt = 0; mt < 2; mt++) {
                const int r0 = wm * 32 + mt * 16 + gq;
                float v0 = As[(k0 + tig) * A_STR + r0];
                float v1 = As[(k0 + tig) * A_STR + r0 + 8];
                float v2 = As[(k0 + tig + 4) * A_STR + r0];
                float v3 = As[(k0 + tig + 4) * A_STR + r0 + 8];
                if (docvt) {
                    a[mt][0] = rna_tf32(v0); a[mt][1] = rna_tf32(v1);
                    a[mt][2] = rna_tf32(v2); a[mt][3] = rna_tf32(v3);
                } else {
                    a[mt][0] = __float_as_uint(v0); a[mt][1] = __float_as_uint(v1);
                    a[mt][2] = __float_as_uint(v2); a[mt][3] = __float_as_uint(v3);
                }
            }
            #pragma unroll
            for (int nt = 0; nt < 4; nt++) {
                const int c0 = wn * 32 + nt * 8 + gq;
                uint32_t b[2];
                b[0] = __float_as_uint(Bs[c0 * B_STR + k0 + tig]);
                b[1] = __float_as_uint(Bs[c0 * B_STR + k0 + tig + 4]);
                mma8(acc[0][nt], a[0], b);
                mma8(acc[1][nt], a[1], b);
            }
        }
    }
    __syncthreads();     // all mma done -> A bufs reusable as H2 stage

    // ---- shuffle epilogue: pair (i,f) with (g,o) via lane^1 ----
    float* H2 = smf + OFF_A;            // 16 units x H_STR
    const int mymt = tig & 1;
    const int r0e = wm * 32 + mymt * 16 + gq;
    #pragma unroll
    for (int nt = 0; nt < 4; nt++) {
        const int u = wn * 8 + nt * 2 + (tig >> 1);
        float oth[4];
        #pragma unroll
        for (int e = 0; e < 4; e++)
            oth[e] = __shfl_xor_sync(0xffffffffu, acc[mymt ^ 1][nt][e], 1);
        const float b0 = smf[OFF_BIAS + 4 * u + 0];
        const float b1 = smf[OFF_BIAS + 4 * u + 1];
        const float b2 = smf[OFF_BIAS + 4 * u + 2];
        const float b3 = smf[OFF_BIAS + 4 * u + 3];
        #pragma unroll
        for (int e2 = 0; e2 < 2; e2++) {
            const float ow0 = acc[mymt][nt][2 * e2], ow1 = acc[mymt][nt][2 * e2 + 1];
            const float ot0 = oth[2 * e2],           ot1 = oth[2 * e2 + 1];
            float gi, gf, gg, go;
            if (mymt == 0) { gi = ow0; gf = ow1; gg = ot0; go = ot1; }
            else           { gg = ow0; go = ow1; gi = ot0; gf = ot1; }
            gi += b0; gf += b1; gg += b2; go += b3;
            const int row = r0e + 8 * e2;
            const size_t ci = (size_t)(j * 16 + u) * NB + n0 + row;
            const float cold = g_Cbuf[ci];
            const float cn = sigf(gf) * cold + sigf(gi) * tanhf_(gg);
            g_Cbuf[ci] = cn;
            H2[u * H_STR + row] = sigf(go) * tanhf_(cn);
        }
    }
    __syncthreads();

    // ---- h-state writeback (h-major, pre-rounded to tf32) ----
    #pragma unroll
    for (int q = 0; q < 2; q++) {
        const int u = wid * 2 + q;
        #pragma unroll
        for (int mk = 0; mk < 4; mk++) {
            const int m = mk * 32 + lane;
            hnext[(size_t)(j * 16 + u) * NB + n0 + m] =
                __uint_as_float(rna_tf32(H2[u * H_STR + m]));
        }
    }
    // ---- output: out[n][t][h], 64B contiguous per row (16 h per CTA) ----
    const int hh = lane & 15, rp = lane >> 4;
    #pragma unroll
    for (int i2 = 0; i2 < 8; i2++) {
        const int mr = wid * 16 + i2 * 2 + rp;
        out[(size_t)(n0 + mr) * TOUT * HD + (size_t)t_out * HD + j * 16 + hh] =
            H2[hh * H_STR + mr];
    }
}

// ---------------------------------------------------------------------------
// launch: prep + 60 K=256 steps + 54 K=128 steps
// ---------------------------------------------------------------------------
extern "C" void kernel_launch(void* const* d_in, const int* in_sizes, int n_in,
                              void* d_out, int out_size) {
    const float* img = (const float*)d_in[0];
    const float* Wih = (const float*)d_in[2];
    const float* Whh = (const float*)d_in[3];
    const float* bih = (const float*)d_in[4];
    const float* bhh = (const float*)d_in[5];
    float* out = (float*)d_out;

    const int T    = in_sizes[0] / (HD * NB);       // 60
    const int TOUT = out_size / (NB * HD);          // 114

    void *h0p, *h1p;
    cudaGetSymbolAddress(&h0p, g_Hbuf0);
    cudaGetSymbolAddress(&h1p, g_Hbuf1);
    float* hb[2] = {(float*)h0p, (float*)h1p};

    cudaFuncSetAttribute((const void*)lstm_step<8>,
                         cudaFuncAttributeMaxDynamicSharedMemorySize, SM_BYTES);
    cudaFuncSetAttribute((const void*)lstm_step<4>,
                         cudaFuncAttributeMaxDynamicSharedMemorySize, SM_BYTES);

    prep_kernel<<<512, 256>>>(Wih, Whh, bih, bhh);

    dim3 grid(8, NB / 128);                         // 256 CTAs, 2/SM
    for (int t = 0; t < TOUT; t++) {
        float* hp = hb[t & 1];
        float* hn = hb[(t + 1) & 1];
        if (t < T) {
            lstm_step<8><<<grid, 256, SM_BYTES>>>(
                img + (size_t)t * HD * NB, hp, hn, out, t, TOUT);
        } else {
            lstm_step<4><<<grid, 256, SM_BYTES>>>(
                nullptr, hp, hn, out, t, TOUT);
        }
    }
}